// round 10
// baseline (speedup 1.0000x reference)
#include <cuda_runtime.h>
#include <math.h>

// ---------------------------------------------------------------------------
// ZBLRepulsion: per-edge repulsion energy + segment_sum over receivers.
//   N_NODES = 1,000,000   N_EDGES = 32,000,000   N_SPECIES = 100
//
// Design (R10):
//   prep : params (incl. p, ln d) + per-node z byte (z = index_to_z[species],
//          1..100 fits u8); zero output. 8 nodes/thread, 512-thr blocks.
//   edge : 4 edges/thread, early REDs (R8-validated), float4/int4 L2-stream
//          loads, 8 batched random u8 z-gathers (1MB, L1 ~22% hit).
//          NO smem table: d*z^p = __expf(fmaf(p, __logf(z), ln d)) — moves
//          ~50K cyc/SM of random-LDS bank-conflict wavefronts off the
//          saturated l1tex pipe onto idle MUFU (13 MUFU/edge ≈ 176K cyc/SM,
//          well under the ~430K l1tex gather floor).
//
// Floor model (validated R3-R9): l1tex wavefronts bind — 64M random gather
// lanes + 32M spread REDG + streaming; L1/L2 ~90% co-saturated at ~328us.
// ---------------------------------------------------------------------------

#define KE_CONST 14.399645351950548
#define MAX_NODES   1000000

__device__ float  g_params[10];                 // a0..3, c0..3(*KE/2), p, ln d
__device__ uchar4 g_z4[(MAX_NODES + 3) / 4];    // packed per-node z bytes

__device__ __forceinline__ float softplus_f(float x) {
    return fmaxf(x, 0.0f) + log1pf(expf(-fabsf(x)));
}

// ---- kernel 0: fused prep (params in block 0; z-pack + zero, 8/thread) ----
__global__ void __launch_bounds__(512)
zbl_prep_kernel(const float* __restrict__ a_raw,
                const float* __restrict__ c_raw,
                const float* __restrict__ p_raw,
                const float* __restrict__ d_raw,
                const int* __restrict__ index_to_z,
                const int* __restrict__ species,
                float* __restrict__ out,
                int n_nodes, int out_n) {
    if (blockIdx.x == 0 && threadIdx.x == 0) {
        float c[4], csum = 0.0f;
#pragma unroll
        for (int k = 0; k < 4; k++) {
            g_params[k] = softplus_f(a_raw[k]);
            c[k] = softplus_f(c_raw[k]);
            csum += c[k];
        }
        float scale = (float)(KE_CONST * 0.5) / csum;
#pragma unroll
        for (int k = 0; k < 4; k++) g_params[4 + k] = c[k] * scale;
        g_params[8] = softplus_f(p_raw[0]);
        g_params[9] = logf(softplus_f(d_raw[0]));   // ln d (d > 0 always)
    }

    int i = blockIdx.x * blockDim.x + threadIdx.x;
    long long base = (long long)i * 8;      // 8 nodes per thread

    // pack z = index_to_z[species] -> u8 (two uchar4 stores)
    if (base + 7 < n_nodes) {
        int4 s0 = *reinterpret_cast<const int4*>(species + base);
        int4 s1 = *reinterpret_cast<const int4*>(species + base + 4);
        g_z4[(base >> 2) + 0] = make_uchar4(
            (unsigned char)__ldg(index_to_z + s0.x),
            (unsigned char)__ldg(index_to_z + s0.y),
            (unsigned char)__ldg(index_to_z + s0.z),
            (unsigned char)__ldg(index_to_z + s0.w));
        g_z4[(base >> 2) + 1] = make_uchar4(
            (unsigned char)__ldg(index_to_z + s1.x),
            (unsigned char)__ldg(index_to_z + s1.y),
            (unsigned char)__ldg(index_to_z + s1.z),
            (unsigned char)__ldg(index_to_z + s1.w));
    } else if (base < n_nodes) {
        unsigned char* zp = reinterpret_cast<unsigned char*>(g_z4);
        for (long long k = base; k < n_nodes; k++)
            zp[k] = (unsigned char)index_to_z[species[k]];
    }

    // zero output (two float4 stores)
    if (base + 7 < out_n) {
        float4 z = make_float4(0.f, 0.f, 0.f, 0.f);
        *reinterpret_cast<float4*>(out + base)     = z;
        *reinterpret_cast<float4*>(out + base + 4) = z;
    } else if (base < out_n) {
        for (long long k = base; k < out_n; k++) out[k] = 0.0f;
    }
}

// ---- per-edge math (z bytes in, no table) ---------------------------------
__device__ __forceinline__ float zbl_energy(float dd, float ct,
                                            unsigned int zjb, unsigned int zib,
                                            const float* __restrict__ P) {
    float zi = (float)zib;
    float zj = (float)zjb;

    float x = ct * zi * zj * __fdividef(1.0f, dd + 1e-8f);

    // d*z^p = exp(p*ln z + ln d)
    float zpi = __expf(fmaf(P[8], __logf(zi), P[9]));
    float zpj = __expf(fmaf(P[8], __logf(zj), P[9]));
    float rzd = dd * (zpi + zpj);

    float y = P[4] * __expf(-P[0] * rzd)
            + P[5] * __expf(-P[1] * rzd)
            + P[6] * __expf(-P[2] * rzd)
            + P[7] * __expf(-P[3] * rzd);

    float sd = dd * (1.0f / 1.5f);
    float e1 = __expf(-__fdividef(1.0f, fmaxf(sd, 1e-8f)));
    float e2 = __expf(-__fdividef(1.0f, fmaxf(1.0f - sd, 1e-8f)));
    float w  = __fdividef(e2, e1 + e2);

    return w * x * y;
}

// ---- kernel 1: edge loop, 4 edges/thread, early REDs, no smem -------------
__global__ void __launch_bounds__(256)
zbl_edge_kernel(const float* __restrict__ distances,
                const float* __restrict__ cutoffs,
                const int* __restrict__ senders,
                const int* __restrict__ receivers,
                float* __restrict__ out,
                int n_edges) {
    float P[10];
#pragma unroll
    for (int k = 0; k < 10; k++) P[k] = g_params[k];

    const unsigned char* zb = reinterpret_cast<const unsigned char*>(g_z4);

    int i  = blockIdx.x * blockDim.x + threadIdx.x;
    long long e0 = (long long)i * 4;
    if (e0 >= n_edges) return;

    if (e0 + 3 < n_edges) {
        // streaming loads: L2-only, keep L1 for the z gathers
        float4 d4 = __ldcg(reinterpret_cast<const float4*>(distances + e0));
        float4 c4 = __ldcg(reinterpret_cast<const float4*>(cutoffs   + e0));
        int4   s4 = __ldcg(reinterpret_cast<const int4*>(senders    + e0));
        int4   r4 = __ldcg(reinterpret_cast<const int4*>(receivers  + e0));

        // all 8 gathers in flight before compute
        unsigned int sa = __ldg(zb + s4.x), ra = __ldg(zb + r4.x);
        unsigned int sb = __ldg(zb + s4.y), rb = __ldg(zb + r4.y);
        unsigned int sc = __ldg(zb + s4.z), rc = __ldg(zb + r4.z);
        unsigned int sd_ = __ldg(zb + s4.w), rd = __ldg(zb + r4.w);

        // compute + fire each RED as soon as its value is ready
        float va = zbl_energy(d4.x, c4.x, sa, ra, P);
        atomicAdd(out + r4.x, va);
        float vb = zbl_energy(d4.y, c4.y, sb, rb, P);
        atomicAdd(out + r4.y, vb);
        float vc = zbl_energy(d4.z, c4.z, sc, rc, P);
        atomicAdd(out + r4.z, vc);
        float vd = zbl_energy(d4.w, c4.w, sd_, rd, P);
        atomicAdd(out + r4.w, vd);
    } else {
        for (long long e = e0; e < n_edges; e++) {
            unsigned int si = zb[senders[e]];
            unsigned int ri = zb[receivers[e]];
            float v = zbl_energy(distances[e], cutoffs[e], si, ri, P);
            atomicAdd(out + receivers[e], v);
        }
    }
}

// ---------------------------------------------------------------------------
extern "C" void kernel_launch(void* const* d_in, const int* in_sizes, int n_in,
                              void* d_out, int out_size) {
    const int*   node_species = (const int*)  d_in[0];
    const float* distances    = (const float*)d_in[1];
    const float* cutoffs      = (const float*)d_in[2];
    const int*   senders      = (const int*)  d_in[3];
    const int*   receivers    = (const int*)  d_in[4];
    const int*   index_to_z   = (const int*)  d_in[5];
    const float* a_raw        = (const float*)d_in[6];
    const float* c_raw        = (const float*)d_in[7];
    const float* p_raw        = (const float*)d_in[8];
    const float* d_raw        = (const float*)d_in[9];

    int n_nodes = in_sizes[0];
    int n_edges = in_sizes[1];
    float* out  = (float*)d_out;

    {
        int n = (n_nodes > out_size) ? n_nodes : out_size;
        long long octs = ((long long)n + 7) / 8;
        int threads = 512;
        int blocks  = (int)((octs + threads - 1) / threads);
        zbl_prep_kernel<<<blocks, threads>>>(a_raw, c_raw, p_raw, d_raw,
                                             index_to_z, node_species, out,
                                             n_nodes, out_size);
    }

    {
        int threads = 256;
        long long quads = ((long long)n_edges + 3) / 4;
        int blocks  = (int)((quads + threads - 1) / threads);
        zbl_edge_kernel<<<blocks, threads>>>(distances, cutoffs, senders,
                                             receivers, out, n_edges);
    }
}